// round 15
// baseline (speedup 1.0000x reference)
#include <cuda_runtime.h>
#include <cuda_fp16.h>
#include <cstdint>

// out[b,t] = cumsum_t( relu(x @ Wh^T + bh) ) + (x @ Wb^T + bb)
//   x [16384,1024] f32, Wh [512,1024] f32, bh[512], Wb[1,1024], bb[1]
//
// fp16 mma.sync m16n8k16. Main kernel (R14, unchanged 56us): CTA = 32 rows x
// 512 cols, 256 threads, 2 CTAs/SM, warp-independent mainloop (per-warp
// cp.async A-rings + direct-LDG B, zero CTA barriers).
// R15: prepass -> ONE massively-parallel no-loop kernel (8448 blocks):
//   blocks 0..8191: (tile, chunk-pair) of x -> fp16 A-fragment order
//     (smem-staged, coalesced) + deterministic base partials g_bp
//   blocks 8192..8447: (chunk, row-group) of Wh -> B-fragment order
//     (smem-staged, coalesced)

#define DDIM   1024
#define TDIM   512
#define BROWS  16384
#define MTILE  32
#define NCH    32
#define NTHREADS 256

__device__ __half g_whs[TDIM * DDIM];   // B: [chunk][jg][lane][8 halfs]
__device__ __half g_xh[BROWS * DDIM];   // A: [tile][chunk][(i,G)][lane][8 halfs]
__device__ float  g_bp[(BROWS / MTILE) * MTILE * NCH];  // [tile][row32][chunk]

__device__ __forceinline__ void mma_f16(float* c, uint32_t a0, uint32_t a1,
                                        uint32_t a2, uint32_t a3,
                                        uint32_t b0, uint32_t b1) {
    asm volatile(
        "mma.sync.aligned.m16n8k16.row.col.f32.f16.f16.f32 "
        "{%0,%1,%2,%3}, {%4,%5,%6,%7}, {%8,%9}, {%0,%1,%2,%3};"
        : "+f"(c[0]), "+f"(c[1]), "+f"(c[2]), "+f"(c[3])
        : "r"(a0), "r"(a1), "r"(a2), "r"(a3), "r"(b0), "r"(b1));
}
__device__ __forceinline__ void cp16(void* dst_s, const void* src_g) {
    uint32_t d = (uint32_t)__cvta_generic_to_shared(dst_s);
    asm volatile("cp.async.cg.shared.global [%0], [%1], 16;" :: "r"(d), "l"(src_g));
}

// ---- merged no-loop prepass ----
__global__ void __launch_bounds__(256) prep_all_kernel(const float* __restrict__ x,
                                                       const float* __restrict__ Wh,
                                                       const float* __restrict__ Wb) {
    __shared__ __half sbuf[2048];
    const int b = blockIdx.x;
    const int t = threadIdx.x;

    if (b < 8192) {
        // ---- x: tile = b>>4, chunk pair cp = b&15 ----
        const int tile = b >> 4;
        const int cp   = b & 15;
        const int cl = t >> 7;          // which chunk of the pair
        const int tl = t & 127;
        const int r  = tl >> 2;         // row 0..31
        const int q  = tl & 3;          // 8-float k group
        const int chunk = cp * 2 + cl;
        const int gk = chunk * 32 + q * 8;
        const int grow = tile * 32 + r;

        float4 v0 = *(const float4*)(x + (size_t)grow * DDIM + gk);
        float4 v1 = *(const float4*)(x + (size_t)grow * DDIM + gk + 4);
        float4 w0 = *(const float4*)(Wb + gk);
        float4 w1 = *(const float4*)(Wb + gk + 4);

        float p = v0.x * w0.x + v0.y * w0.y + v0.z * w0.z + v0.w * w0.w
                + v1.x * w1.x + v1.y * w1.y + v1.z * w1.z + v1.w * w1.w;
        p += __shfl_down_sync(0xffffffffu, p, 2, 4);
        p += __shfl_down_sync(0xffffffffu, p, 1, 4);
        if (q == 0) g_bp[tile * 1024 + r * 32 + chunk] = p;

        __half* sb = sbuf + cl * 1024;
        const int ii = (r >> 4) & 1, rh = (r >> 3) & 1, l4r = r & 7;
        #pragma unroll
        for (int e = 0; e < 8; e++) {
            int k5 = q * 8 + e;
            int G = (k5 >> 4) & 1, u = (k5 >> 3) & 1, lk = (k5 & 7) >> 1, w_ = k5 & 1;
            float f = (e < 4) ? ((const float*)&v0)[e] : ((const float*)&v1)[e - 4];
            sb[(ii * 2 + G) * 256 + (4 * l4r + lk) * 8 + 4 * u + 2 * rh + w_] =
                __float2half_rn(f);
        }
        __syncthreads();
        *(uint4*)((char*)g_xh + (size_t)(tile * 32 + cp * 2) * 2048 + t * 16) =
            *(const uint4*)((const char*)sbuf + t * 16);
    } else {
        // ---- Wh: c = (b-8192)>>3, row group rg8 = (b-8192)&7 (64 rows) ----
        const int bb_ = b - 8192;
        const int c   = bb_ >> 3;
        const int rg8 = bb_ & 7;
        const int rl = t >> 2;          // 0..63 local row
        const int q  = t & 3;
        const int T  = rg8 * 64 + rl;
        const float* wrow = Wh + (size_t)T * DDIM + c * 32 + q * 8;
        float4 v0 = *(const float4*)(wrow);
        float4 v1 = *(const float4*)(wrow + 4);

        const int jg_l = rl >> 3;       // 0..7
        const int l4 = T & 7;
        #pragma unroll
        for (int e = 0; e < 8; e++) {
            int k5 = q * 8 + e;
            int G = (k5 >> 4) & 1, u = (k5 >> 3) & 1, lk = (k5 & 7) >> 1, w_ = k5 & 1;
            float f = (e < 4) ? ((const float*)&v0)[e] : ((const float*)&v1)[e - 4];
            sbuf[jg_l * 256 + (4 * l4 + lk) * 8 + 4 * G + 2 * u + w_] =
                __float2half_rn(f);
        }
        __syncthreads();
        *(uint4*)((char*)g_whs + (size_t)c * 32768 + rg8 * 4096 + t * 16) =
            *(const uint4*)((const char*)sbuf + t * 16);
    }
}

__global__ void __launch_bounds__(NTHREADS, 2)
surv_f16j_kernel(const float* __restrict__ bh,
                 const float* __restrict__ bb,
                 float* __restrict__ out)
{
    __shared__ __align__(16) char As[8 * 4 * 2048];   // per-warp 4-stage A rings
    __shared__ float seg_s[MTILE * 8];
    __shared__ float base_s[MTILE];

    const int tid  = threadIdx.x;
    const int nw   = tid >> 5;
    const int lane = tid & 31;
    const int l4   = lane >> 2;
    const int lk   = lane & 3;
    const int tile = blockIdx.x;
    const int row0 = tile * MTILE;

    const char* axsrc = (const char*)g_xh + (size_t)tile * 65536 + lane * 16;
    char* aring = As + nw * 8192 + lane * 16;
    const char* bgm = (const char*)g_whs + nw * 4096 + lane * 16;

    float acc[2][8][4];
    #pragma unroll
    for (int i = 0; i < 2; i++)
        #pragma unroll
        for (int j = 0; j < 8; j++)
            #pragma unroll
            for (int q = 0; q < 4; q++) acc[i][j][q] = 0.f;

    // prologue: A stages 0..2, B chunk 0
    #pragma unroll
    for (int s = 0; s < 3; s++) {
        const char* src = axsrc + (size_t)s * 2048;
        char* dst = aring + s * 2048;
        #pragma unroll
        for (int i = 0; i < 4; i++)
            cp16(dst + i * 512, src + i * 512);
        asm volatile("cp.async.commit_group;" ::: "memory");
    }
    uint4 LB[8];
    #pragma unroll
    for (int j = 0; j < 8; j++)
        LB[j] = *(const uint4*)(bgm + j * 512);

    // ---- mainloop: warp-independent, no CTA barriers ----
    #pragma unroll 1
    for (int c = 0; c < NCH; c++) {
        if (c <= NCH - 3)      asm volatile("cp.async.wait_group 2;" ::: "memory");
        else if (c == NCH - 2) asm volatile("cp.async.wait_group 1;" ::: "memory");
        else                   asm volatile("cp.async.wait_group 0;" ::: "memory");
        __syncwarp();

        const char* xaddr = aring + (c & 3) * 2048;
        uint4 LA00 = *(const uint4*)(xaddr);
        uint4 LA01 = *(const uint4*)(xaddr + 512);
        uint4 LA10 = *(const uint4*)(xaddr + 1024);
        uint4 LA11 = *(const uint4*)(xaddr + 1536);

        if (c + 3 < NCH) {   // refill ring stage (c+3)&3
            const char* src = axsrc + (size_t)(c + 3) * 2048;
            char* dst = aring + ((c + 3) & 3) * 2048;
            #pragma unroll
            for (int i = 0; i < 4; i++)
                cp16(dst + i * 512, src + i * 512);
            asm volatile("cp.async.commit_group;" ::: "memory");
        }

        const char* bnext = bgm + (size_t)((c + 1 < NCH) ? (c + 1) : c) * 32768;
        #pragma unroll
        for (int j = 0; j < 8; j++) {
            uint4 b = LB[j];
            mma_f16(acc[0][j], LA00.x, LA00.y, LA00.z, LA00.w, b.x, b.y);
            mma_f16(acc[1][j], LA10.x, LA10.y, LA10.z, LA10.w, b.x, b.y);
            mma_f16(acc[0][j], LA01.x, LA01.y, LA01.z, LA01.w, b.z, b.w);
            mma_f16(acc[1][j], LA11.x, LA11.y, LA11.z, LA11.w, b.z, b.w);
            LB[j] = *(const uint4*)(bnext + j * 512);
        }
    }

    // ---- base: reduce per-chunk partials in fixed order ----
    {
        const int r  = tid >> 3;       // 0..31
        const int kq = tid & 7;
        const float* bp = g_bp + tile * 1024 + r * 32 + kq * 4;
        float4 p4 = *(const float4*)bp;
        float p = (p4.x + p4.y) + (p4.z + p4.w);
        p += __shfl_down_sync(0xffffffffu, p, 4, 8);
        p += __shfl_down_sync(0xffffffffu, p, 2, 8);
        p += __shfl_down_sync(0xffffffffu, p, 1, 8);
        if (kq == 0) base_s[r] = p;
    }

    // ---- per-row segmented scan over this warp's 64 cols ----
    float2 bhv[8];
    #pragma unroll
    for (int j = 0; j < 8; j++)
        bhv[j] = __ldg((const float2*)(bh + nw * 64 + 8 * j + 2 * lk));

    #pragma unroll
    for (int i = 0; i < 2; i++) {
        #pragma unroll
        for (int hh = 0; hh < 2; hh++) {
            const int r = 16 * i + 8 * hh + l4;
            float carry = 0.f;
            #pragma unroll
            for (int j = 0; j < 8; j++) {
                float v0 = fmaxf(acc[i][j][2 * hh]     + bhv[j].x, 0.f);
                float v1 = fmaxf(acc[i][j][2 * hh + 1] + bhv[j].y, 0.f);
                float p = v0 + v1;
                float incl = p, t;
                t = __shfl_up_sync(0xffffffffu, incl, 1, 4); if (lk >= 1) incl += t;
                t = __shfl_up_sync(0xffffffffu, incl, 2, 4); if (lk >= 2) incl += t;
                float excl = incl - p;
                acc[i][j][2 * hh]     = carry + excl + v0;
                acc[i][j][2 * hh + 1] = carry + incl;
                carry += __shfl_sync(0xffffffffu, incl, 3, 4);
            }
            if (lk == 0) seg_s[r * 8 + nw] = carry;
        }
    }
    __syncthreads();   // the ONE CTA barrier

    // ---- cross-warp segment prefix + base, store ----
    const float bbv = bb[0];
    #pragma unroll
    for (int i = 0; i < 2; i++) {
        #pragma unroll
        for (int hh = 0; hh < 2; hh++) {
            const int r = 16 * i + 8 * hh + l4;
            float g = base_s[r] + bbv;
            #pragma unroll
            for (int s = 0; s < 8; s++)
                if (s < nw) g += seg_s[r * 8 + s];
            float* orow = out + (size_t)(row0 + r) * TDIM + nw * 64 + 2 * lk;
            #pragma unroll
            for (int j = 0; j < 8; j++) {
                float2 o;
                o.x = acc[i][j][2 * hh]     + g;
                o.y = acc[i][j][2 * hh + 1] + g;
                *(float2*)(orow + 8 * j) = o;
            }
        }
    }
}

extern "C" void kernel_launch(void* const* d_in, const int* in_sizes, int n_in,
                              void* d_out, int out_size)
{
    const float* x  = (const float*)d_in[0];
    const float* Wh = (const float*)d_in[1];
    const float* bh = (const float*)d_in[2];
    const float* Wb = (const float*)d_in[3];
    const float* bb = (const float*)d_in[4];
    float* out = (float*)d_out;
    (void)in_sizes; (void)n_in; (void)out_size;

    prep_all_kernel<<<8448, 256>>>(x, Wh, Wb);
    surv_f16j_kernel<<<BROWS / MTILE, NTHREADS>>>(bh, bb, out);
}